// round 15
// baseline (speedup 1.0000x reference)
#include <cuda_runtime.h>
#include <cuda_bf16.h>
#include <cstdint>

#define BATCH 32
#define LEN   1024
#define CH    512
#define NLEV  4
#define OUTN  11
#define KTOT  1024
#define BK    32            // ci per chunk
#define NCH   16            // ci chunks (both taps done per chunk)
#define TM    128
#define TN    128

// ---- global scratch (device globals; no allocations allowed) ----
__device__ float g_a[BATCH*LEN*CH];        // 64MB act buffer A (tf32-rounded fp32)
__device__ float g_b[BATCH*LEN*CH];        // 64MB act buffer B
__device__ float g_w[NLEV*2*CH*KTOT];      // 16MB packed weights [lev][conv][co][k], tf32-rounded

// ============================================================================
// helpers
// ============================================================================
__device__ __forceinline__ uint32_t smem_u32(const void* p) {
    uint32_t a;
    asm("{ .reg .u64 t; cvta.to.shared.u64 t, %1; cvt.u32.u64 %0, t; }" : "=r"(a) : "l"(p));
    return a;
}

__device__ __forceinline__ void cpa16(uint32_t dst, const void* src, uint32_t sz) {
    asm volatile("cp.async.cg.shared.global [%0], [%1], 16, %2;"
                 :: "r"(dst), "l"(src), "r"(sz) : "memory");
}

__device__ __forceinline__ void ldsm4(uint32_t* r, uint32_t a) {
    asm volatile("ldmatrix.sync.aligned.m8n8.x4.shared.b16 {%0,%1,%2,%3}, [%4];"
                 : "=r"(r[0]), "=r"(r[1]), "=r"(r[2]), "=r"(r[3]) : "r"(a));
}

__device__ __forceinline__ void mma_tf32(float* d, const uint32_t* a, const uint32_t* b) {
    asm volatile("mma.sync.aligned.m16n8k8.row.col.f32.tf32.tf32.f32 "
                 "{%0,%1,%2,%3}, {%4,%5,%6,%7}, {%8,%9}, {%0,%1,%2,%3};"
                 : "+f"(d[0]), "+f"(d[1]), "+f"(d[2]), "+f"(d[3])
                 : "r"(a[0]), "r"(a[1]), "r"(a[2]), "r"(a[3]), "r"(b[0]), "r"(b[1]));
}

// round-to-nearest tf32 returned as fp32
__device__ __forceinline__ float tf32r(float v) {
    uint32_t u;
    asm("cvt.rna.tf32.f32 %0, %1;" : "=r"(u) : "f"(v));
    return __uint_as_float(u);
}

// ============================================================================
// repack weights -> [lev][conv][co][k] k-major tf32; k<CH: tap1, k>=CH: tap0
// ============================================================================
__global__ void repack_kernel(const float* __restrict__ w1, const float* __restrict__ w2) {
    int idx = blockIdx.x * blockDim.x + threadIdx.x;
    const int total = NLEV * 2 * CH * KTOT;
    if (idx >= total) return;
    int k    = idx % KTOT;
    int co   = (idx / KTOT) % CH;
    int conv = (idx / (KTOT * CH)) % 2;
    int lev  = idx / (KTOT * CH * 2);
    const float* w = conv ? w2 : w1;
    int tap = (k < CH) ? 1 : 0;
    int ci  = k & (CH - 1);
    g_w[idx] = tf32r(w[((lev * CH + co) * CH + ci) * 2 + tap]);
}

// ============================================================================
// embedding gather -> act buffer A, [b][l][c] layout, tf32-rounded fp32
// ============================================================================
__global__ void embed_kernel(const int* __restrict__ x, const float* __restrict__ emb) {
    int idx = blockIdx.x * blockDim.x + threadIdx.x;
    int c = idx % CH;
    int bl = idx / CH;
    int tok = x[bl];
    g_a[idx] = tf32r(emb[tok * CH + c]);
}

// ============================================================================
// conv as TF32 HMMA GEMM with tap-sharing and interleaved tap streams:
//   One A tile of (128+d) rows covers global l in [l0-d, l0+128).
//   smem A row s  <->  global l = l0 - d + s.
//   tap1 (W tile 0, k< CH): output row r uses s = r + d  (l = l0 + r)
//   tap0 (W tile 1, k>=CH): output row r uses s = r      (l = l0 + r - d)
// Per ks: load A frags for BOTH taps, then per W j-tile load both tap W
// fragments and issue both taps' MMAs -> wide independent LDSM streams.
// ============================================================================
#define A_BYTES 18432           // 136 rows x 128B, padded
#define OFF_A   0
#define OFF_W   18432           // two 16KB W tiles: [0]=tap1 (k<CH), [1]=tap0 (k>=CH)
#define SST     (18432 + 32768) // 51200 per stage
#define NSTAGE  2
#define SMEM_SZ (1024 + NSTAGE*SST)

__global__ __launch_bounds__(256, 2) void conv_hmma_kernel(int wbase, const float* __restrict__ bias,
                                                           int d, int dir) {
    extern __shared__ char sm[];
    const uint32_t sb    = smem_u32(sm);
    const uint32_t tiles = sb + 1024;

    const float* __restrict__ act = dir ? g_b : g_a;
    float*       __restrict__ out = dir ? g_a : g_b;

    const int tid    = threadIdx.x;
    const int lane   = tid & 31;
    const int wid    = tid >> 5;
    const int warp_m = wid & 3;
    const int warp_n = wid >> 2;
    const int l0     = blockIdx.x * TM;
    const int co0    = blockIdx.y * TN;
    const int b      = blockIdx.z;

    if (tid < 128) ((float*)sm)[tid] = bias[co0 + tid];

    const int nrows = TM + d;   // valid A rows: s in [0, nrows)

    // ---- chunk loader (cp.async): A 136 rows + W 256 rows (two tap tiles) ----
    auto load_chunk = [&](int c) {
        const uint32_t st = tiles + (c & 1) * SST;
        const int cb      = c * BK;
        // A: 1088 slots (136 rows x 8 segs)
#pragma unroll
        for (int i = 0; i < 5; i++) {
            int u = tid + 256 * i;
            if (u < 1088) {
                const int s = u >> 3, seg = u & 7;
                const uint32_t sw = (uint32_t)(s * 128 + ((seg ^ (s & 7)) << 4));
                int ls = l0 + s - d;
                uint32_t pr = (ls >= 0 && s < nrows) ? 16u : 0u;
                if (pr == 0) ls = 0;
                cpa16(st + OFF_A + sw, act + (b * LEN + ls) * CH + cb + seg * 4, pr);
            }
        }
        // W: 2048 slots; r<128 -> tap1 tile (k=cb), r>=128 -> tap0 tile (k=CH+cb)
#pragma unroll
        for (int i = 0; i < 8; i++) {
            const int u = tid + 256 * i;
            const int r = u >> 3, seg = u & 7;
            const int rr = r & 127;
            const int tile = r >> 7;
            const uint32_t sw = (uint32_t)(tile * 16384 + rr * 128 + ((seg ^ (rr & 7)) << 4));
            const int koff = cb + tile * CH;
            cpa16(st + OFF_W + sw, g_w + wbase + (co0 + rr) * KTOT + koff + seg * 4, 16u);
        }
        asm volatile("cp.async.commit_group;" ::: "memory");
    };

    float acc[2][8][4];
#pragma unroll
    for (int mt = 0; mt < 2; mt++)
#pragma unroll
        for (int nt = 0; nt < 8; nt++)
#pragma unroll
            for (int q = 0; q < 4; q++) acc[mt][nt][q] = 0.f;

    load_chunk(0);
    load_chunk(1);

    // tf32 fragment address components
    const int a_rh = ((lane >> 3) & 1) * 8 + (lane & 7);
    const int a_kh = (lane >> 4) & 1;
    const int w_rh = ((lane >> 4) & 1) * 8 + (lane & 7);
    const int w_kh = (lane >> 3) & 1;

    for (int c = 0; c < NCH; c++) {
        if (c + 1 < NCH) asm volatile("cp.async.wait_group 1;" ::: "memory");
        else             asm volatile("cp.async.wait_group 0;" ::: "memory");
        __syncthreads();

        const uint32_t st = tiles + (c & 1) * SST;
        const uint32_t AT = st + OFF_A;
        const uint32_t W1 = st + OFF_W;              // tap1 tile (k<CH), A s = r + d
        const uint32_t W0 = st + OFF_W + 16384;      // tap0 tile (k>=CH), A s = r

#pragma unroll
        for (int ks = 0; ks < 4; ks++) {
            // A fragments for BOTH taps (independent ldsm stream)
            uint32_t a1[2][4], a0[2][4];
            const int akb = ks * 32 + a_kh * 16;
#pragma unroll
            for (int mt = 0; mt < 2; mt++) {
                const int r1 = warp_m * 32 + mt * 16 + a_rh + d;
                const int r0 = warp_m * 32 + mt * 16 + a_rh;
                ldsm4(a1[mt], AT + (uint32_t)(r1 * 128 + (((akb >> 4) ^ (r1 & 7)) << 4)));
                ldsm4(a0[mt], AT + (uint32_t)(r0 * 128 + (((akb >> 4) ^ (r0 & 7)) << 4)));
            }
            const int wkb = ks * 32 + w_kh * 16;
#pragma unroll
            for (int j = 0; j < 4; j++) {
                uint32_t w1[4], w0[4];
                const int rr = warp_n * 64 + j * 16 + w_rh;
                const uint32_t off = (uint32_t)(rr * 128 + (((wkb >> 4) ^ (rr & 7)) << 4));
                ldsm4(w1, W1 + off);
                ldsm4(w0, W0 + off);
#pragma unroll
                for (int mt = 0; mt < 2; mt++) {
                    mma_tf32(acc[mt][j * 2 + 0], a1[mt], &w1[0]);
                    mma_tf32(acc[mt][j * 2 + 1], a1[mt], &w1[2]);
                    mma_tf32(acc[mt][j * 2 + 0], a0[mt], &w0[0]);
                    mma_tf32(acc[mt][j * 2 + 1], a0[mt], &w0[2]);
                }
            }
        }
        __syncthreads();
        if (c + 2 < NCH) load_chunk(c + 2);
    }

    // ---- epilogue: bias + relu (+ residual + relu), tf32-round, store fp32 ----
    const float* bs = (const float*)sm;
#pragma unroll
    for (int mt = 0; mt < 2; mt++) {
        const int rbase = warp_m * 32 + mt * 16 + (lane >> 2);
#pragma unroll
        for (int half = 0; half < 2; half++) {
            const int row = rbase + half * 8;
            const int l   = l0 + row;
            const int rowoff = (b * LEN + l) * CH + co0;
#pragma unroll
            for (int nt = 0; nt < 8; nt++) {
                const int c0 = warp_n * 64 + nt * 8 + (lane & 3) * 2;
                float v0 = fmaxf(acc[mt][nt][half * 2 + 0] + bs[c0],     0.f);
                float v1 = fmaxf(acc[mt][nt][half * 2 + 1] + bs[c0 + 1], 0.f);
                const int off = rowoff + c0;
                if (dir) {
                    float2 r2 = *(const float2*)(g_a + off);
                    v0 = fmaxf(v0 + r2.x, 0.f);
                    v1 = fmaxf(v1 + r2.y, 0.f);
                }
                float2 o2;
                o2.x = tf32r(v0);
                o2.y = tf32r(v1);
                *(float2*)(out + off) = o2;
            }
        }
    }
}

// ============================================================================
// decoder: y[b,l,o] = mask ? sum_c h(b,l,c) * dec_w[o,c] + dec_b[o] : 0
// ============================================================================
__global__ __launch_bounds__(128) void decode_kernel(const int* __restrict__ mask,
                                                     const float* __restrict__ dec_w,
                                                     const float* __restrict__ dec_b,
                                                     float* __restrict__ y) {
    __shared__ float sw[OUTN * CH];
    const int tid = threadIdx.x;
    for (int i = tid; i < OUTN * CH; i += 128) sw[i] = dec_w[i];
    __syncthreads();

    const int b = blockIdx.y;
    const int l = blockIdx.x * 128 + tid;
    const int base = (b * LEN + l) * CH;

    float acc[OUTN];
#pragma unroll
    for (int o = 0; o < OUTN; o++) acc[o] = 0.f;

    for (int c = 0; c < CH; c += 4) {
        float4 H = *(const float4*)(g_a + base + c);
        const float hv[4] = {H.x, H.y, H.z, H.w};
#pragma unroll
        for (int q = 0; q < 4; q++)
#pragma unroll
            for (int o = 0; o < OUTN; o++) acc[o] = fmaf(hv[q], sw[o * CH + c + q], acc[o]);
    }

    const int mk = mask[b * LEN + l];
    float* yo = y + (b * LEN + l) * OUTN;
#pragma unroll
    for (int o = 0; o < OUTN; o++) yo[o] = mk ? (acc[o] + dec_b[o]) : 0.f;
}

// ============================================================================
// launch
// ============================================================================
extern "C" void kernel_launch(void* const* d_in, const int* in_sizes, int n_in,
                              void* d_out, int out_size) {
    const int*   x     = (const int*)d_in[0];
    const int*   mask  = (const int*)d_in[1];
    const float* emb   = (const float*)d_in[2];
    const float* w1    = (const float*)d_in[3];
    const float* b1    = (const float*)d_in[4];
    const float* w2    = (const float*)d_in[5];
    const float* b2    = (const float*)d_in[6];
    const float* dec_w = (const float*)d_in[7];
    const float* dec_b = (const float*)d_in[8];
    float*       y     = (float*)d_out;

    cudaFuncSetAttribute(conv_hmma_kernel, cudaFuncAttributeMaxDynamicSharedMemorySize, SMEM_SZ);

    // 1) repack weights (tf32-rounded, k-major)
    {
        const int total = NLEV * 2 * CH * KTOT;
        repack_kernel<<<(total + 255) / 256, 256>>>(w1, w2);
    }
    // 2) embedding gather -> act buffer A
    {
        const int total = BATCH * LEN * CH;
        embed_kernel<<<total / 256, 256>>>(x, emb);
    }
    // 3) TCN levels on tensor cores (1xTF32, tap-shared A tile, interleaved taps)
    dim3 grid(LEN / TM, CH / TN, BATCH);
    for (int lev = 0; lev < NLEV; lev++) {
        const int d = 1 << lev;
        const int wb1 = (lev * 2 + 0) * CH * KTOT;
        const int wb2 = (lev * 2 + 1) * CH * KTOT;
        conv_hmma_kernel<<<grid, 256, SMEM_SZ>>>(wb1, b1 + lev * CH, d, 0);  // A -> B
        conv_hmma_kernel<<<grid, 256, SMEM_SZ>>>(wb2, b2 + lev * CH, d, 1);  // B (+res A) -> A
    }
    // 4) decode + mask
    decode_kernel<<<dim3(LEN / 128, BATCH), 128>>>(mask, dec_w, dec_b, y);
}

// round 16
// speedup vs baseline: 1.0125x; 1.0125x over previous
#include <cuda_runtime.h>
#include <cuda_bf16.h>
#include <cstdint>

#define BATCH 32
#define LEN   1024
#define CH    512
#define NLEV  4
#define OUTN  11
#define KTOT  1024
#define BK    32            // ci per chunk
#define NCH   16            // ci chunks (both taps done per chunk)
#define TM    128
#define TN    128

// ---- global scratch (device globals; no allocations allowed) ----
__device__ float g_a[BATCH*LEN*CH];        // 64MB act buffer A (tf32-rounded fp32)
__device__ float g_b[BATCH*LEN*CH];        // 64MB act buffer B
__device__ float g_w[NLEV*2*CH*KTOT];      // 16MB packed weights [lev][conv][co][k], tf32-rounded

// ============================================================================
// helpers
// ============================================================================
__device__ __forceinline__ uint32_t smem_u32(const void* p) {
    uint32_t a;
    asm("{ .reg .u64 t; cvta.to.shared.u64 t, %1; cvt.u32.u64 %0, t; }" : "=r"(a) : "l"(p));
    return a;
}

__device__ __forceinline__ void cpa16(uint32_t dst, const void* src, uint32_t sz) {
    asm volatile("cp.async.cg.shared.global [%0], [%1], 16, %2;"
                 :: "r"(dst), "l"(src), "r"(sz) : "memory");
}

__device__ __forceinline__ void ldsm4(uint32_t* r, uint32_t a) {
    asm volatile("ldmatrix.sync.aligned.m8n8.x4.shared.b16 {%0,%1,%2,%3}, [%4];"
                 : "=r"(r[0]), "=r"(r[1]), "=r"(r[2]), "=r"(r[3]) : "r"(a));
}

__device__ __forceinline__ void mma_tf32(float* d, const uint32_t* a, const uint32_t* b) {
    asm volatile("mma.sync.aligned.m16n8k8.row.col.f32.tf32.tf32.f32 "
                 "{%0,%1,%2,%3}, {%4,%5,%6,%7}, {%8,%9}, {%0,%1,%2,%3};"
                 : "+f"(d[0]), "+f"(d[1]), "+f"(d[2]), "+f"(d[3])
                 : "r"(a[0]), "r"(a[1]), "r"(a[2]), "r"(a[3]), "r"(b[0]), "r"(b[1]));
}

// round-to-nearest tf32 returned as fp32
__device__ __forceinline__ float tf32r(float v) {
    uint32_t u;
    asm("cvt.rna.tf32.f32 %0, %1;" : "=r"(u) : "f"(v));
    return __uint_as_float(u);
}

// ============================================================================
// repack weights -> [lev][conv][co][k] k-major tf32; k<CH: tap1, k>=CH: tap0
// ============================================================================
__global__ void repack_kernel(const float* __restrict__ w1, const float* __restrict__ w2) {
    int idx = blockIdx.x * blockDim.x + threadIdx.x;
    const int total = NLEV * 2 * CH * KTOT;
    if (idx >= total) return;
    int k    = idx % KTOT;
    int co   = (idx / KTOT) % CH;
    int conv = (idx / (KTOT * CH)) % 2;
    int lev  = idx / (KTOT * CH * 2);
    const float* w = conv ? w2 : w1;
    int tap = (k < CH) ? 1 : 0;
    int ci  = k & (CH - 1);
    g_w[idx] = tf32r(w[((lev * CH + co) * CH + ci) * 2 + tap]);
}

// ============================================================================
// embedding gather -> act buffer A, [b][l][c] layout, tf32-rounded fp32
// ============================================================================
__global__ void embed_kernel(const int* __restrict__ x, const float* __restrict__ emb) {
    int idx = blockIdx.x * blockDim.x + threadIdx.x;
    int c = idx % CH;
    int bl = idx / CH;
    int tok = x[bl];
    g_a[idx] = tf32r(emb[tok * CH + c]);
}

// ============================================================================
// conv as TF32 HMMA GEMM, tap-shared A tile, 64x64 warp tiles (4 warps).
//   A tile (128+d) rows: smem row s <-> global l = l0 - d + s.
//   tap1 (W tile 0, k< CH): output row r uses s = r + d
//   tap0 (W tile 1, k>=CH): output row r uses s = r
// 16 ci-chunks; 2 stages; 2 CTAs/SM; 128 threads (warp grid 2x2, tile 64x64).
// ============================================================================
#define OFF_A   0
#define OFF_W   18432           // two 16KB W tiles: [0]=tap1 (k<CH), [1]=tap0 (k>=CH)
#define SST     (18432 + 32768) // 51200 per stage
#define SMEM_SZ (1024 + 2*SST)

__global__ __launch_bounds__(128, 2) void conv_hmma_kernel(int wbase, const float* __restrict__ bias,
                                                           int d, int dir) {
    extern __shared__ char sm[];
    const uint32_t sb    = smem_u32(sm);
    const uint32_t tiles = sb + 1024;

    const float* __restrict__ act = dir ? g_b : g_a;
    float*       __restrict__ out = dir ? g_a : g_b;

    const int tid    = threadIdx.x;
    const int lane   = tid & 31;
    const int wid    = tid >> 5;          // 0..3
    const int warp_m = wid & 1;           // 2 m-tiles of 64
    const int warp_n = wid >> 1;          // 2 n-tiles of 64
    const int l0     = blockIdx.x * TM;
    const int co0    = blockIdx.y * TN;
    const int b      = blockIdx.z;

    ((float*)sm)[tid] = bias[co0 + tid];  // 128 threads -> 128 biases

    const int nrows = TM + d;

    // ---- chunk loader (cp.async): A 136 rows + W 256 rows (two tap tiles) ----
    auto load_chunk = [&](int c) {
        const uint32_t st = tiles + (c & 1) * SST;
        const int cb      = c * BK;
        // A: 1088 slots (136 rows x 8 segs)
#pragma unroll
        for (int i = 0; i < 9; i++) {
            int u = tid + 128 * i;
            if (u < 1088) {
                const int s = u >> 3, seg = u & 7;
                const uint32_t sw = (uint32_t)(s * 128 + ((seg ^ (s & 7)) << 4));
                int ls = l0 + s - d;
                uint32_t pr = (ls >= 0 && s < nrows) ? 16u : 0u;
                if (pr == 0) ls = 0;
                cpa16(st + OFF_A + sw, act + (b * LEN + ls) * CH + cb + seg * 4, pr);
            }
        }
        // W: 2048 slots; r<128 -> tap1 tile (k=cb), r>=128 -> tap0 tile (k=CH+cb)
#pragma unroll
        for (int i = 0; i < 16; i++) {
            const int u = tid + 128 * i;
            const int r = u >> 3, seg = u & 7;
            const int rr = r & 127;
            const int tile = r >> 7;
            const uint32_t sw = (uint32_t)(tile * 16384 + rr * 128 + ((seg ^ (rr & 7)) << 4));
            const int koff = cb + tile * CH;
            cpa16(st + OFF_W + sw, g_w + wbase + (co0 + rr) * KTOT + koff + seg * 4, 16u);
        }
        asm volatile("cp.async.commit_group;" ::: "memory");
    };

    float acc[4][8][4];                   // 128 regs: 4 m-tiles(16) x 8 n-tiles(8) x 4
#pragma unroll
    for (int mt = 0; mt < 4; mt++)
#pragma unroll
        for (int nt = 0; nt < 8; nt++)
#pragma unroll
            for (int q = 0; q < 4; q++) acc[mt][nt][q] = 0.f;

    load_chunk(0);
    load_chunk(1);

    // tf32 fragment address components
    const int a_rh = ((lane >> 3) & 1) * 8 + (lane & 7);
    const int a_kh = (lane >> 4) & 1;
    const int w_rh = ((lane >> 4) & 1) * 8 + (lane & 7);
    const int w_kh = (lane >> 3) & 1;

    for (int c = 0; c < NCH; c++) {
        if (c + 1 < NCH) asm volatile("cp.async.wait_group 1;" ::: "memory");
        else             asm volatile("cp.async.wait_group 0;" ::: "memory");
        __syncthreads();

        const uint32_t st = tiles + (c & 1) * SST;
        const uint32_t AT = st + OFF_A;
        const uint32_t W1 = st + OFF_W;              // tap1 (k<CH), A s = r + d
        const uint32_t W0 = st + OFF_W + 16384;      // tap0 (k>=CH), A s = r

#pragma unroll
        for (int ks = 0; ks < 4; ks++) {
            // A fragments for both taps: 4 m-tiles x 2 taps = 8 ldsm
            uint32_t a1[4][4], a0[4][4];
            const int akb = ks * 32 + a_kh * 16;
#pragma unroll
            for (int mt = 0; mt < 4; mt++) {
                const int r1 = warp_m * 64 + mt * 16 + a_rh + d;
                const int r0 = warp_m * 64 + mt * 16 + a_rh;
                ldsm4(a1[mt], AT + (uint32_t)(r1 * 128 + (((akb >> 4) ^ (r1 & 7)) << 4)));
                ldsm4(a0[mt], AT + (uint32_t)(r0 * 128 + (((akb >> 4) ^ (r0 & 7)) << 4)));
            }
            const int wkb = ks * 32 + w_kh * 16;
#pragma unroll
            for (int j = 0; j < 4; j++) {            // 4 co-tiles of 16
                uint32_t w1[4], w0[4];
                const int rr = warp_n * 64 + j * 16 + w_rh;
                const uint32_t off = (uint32_t)(rr * 128 + (((wkb >> 4) ^ (rr & 7)) << 4));
                ldsm4(w1, W1 + off);
                ldsm4(w0, W0 + off);
#pragma unroll
                for (int mt = 0; mt < 4; mt++) {
                    mma_tf32(acc[mt][j * 2 + 0], a1[mt], &w1[0]);
                    mma_tf32(acc[mt][j * 2 + 1], a1[mt], &w1[2]);
                    mma_tf32(acc[mt][j * 2 + 0], a0[mt], &w0[0]);
                    mma_tf32(acc[mt][j * 2 + 1], a0[mt], &w0[2]);
                }
            }
        }
        __syncthreads();
        if (c + 2 < NCH) load_chunk(c + 2);
    }

    // ---- epilogue: bias + relu (+ residual + relu), tf32-round, store fp32 ----
    const float* bs = (const float*)sm;
#pragma unroll
    for (int mt = 0; mt < 4; mt++) {
        const int rbase = warp_m * 64 + mt * 16 + (lane >> 2);
#pragma unroll
        for (int half = 0; half < 2; half++) {
            const int row = rbase + half * 8;
            const int l   = l0 + row;
            const int rowoff = (b * LEN + l) * CH + co0;
#pragma unroll
            for (int nt = 0; nt < 8; nt++) {
                const int c0 = warp_n * 64 + nt * 8 + (lane & 3) * 2;
                float v0 = fmaxf(acc[mt][nt][half * 2 + 0] + bs[c0],     0.f);
                float v1 = fmaxf(acc[mt][nt][half * 2 + 1] + bs[c0 + 1], 0.f);
                const int off = rowoff + c0;
                if (dir) {
                    float2 r2 = *(const float2*)(g_a + off);
                    v0 = fmaxf(v0 + r2.x, 0.f);
                    v1 = fmaxf(v1 + r2.y, 0.f);
                }
                float2 o2;
                o2.x = tf32r(v0);
                o2.y = tf32r(v1);
                *(float2*)(out + off) = o2;
            }
        }
    }
}

// ============================================================================
// decoder: y[b,l,o] = mask ? sum_c h(b,l,c) * dec_w[o,c] + dec_b[o] : 0
// ============================================================================
__global__ __launch_bounds__(128) void decode_kernel(const int* __restrict__ mask,
                                                     const float* __restrict__ dec_w,
                                                     const float* __restrict__ dec_b,
                                                     float* __restrict__ y) {
    __shared__ float sw[OUTN * CH];
    const int tid = threadIdx.x;
    for (int i = tid; i < OUTN * CH; i += 128) sw[i] = dec_w[i];
    __syncthreads();

    const int b = blockIdx.y;
    const int l = blockIdx.x * 128 + tid;
    const int base = (b * LEN + l) * CH;

    float acc[OUTN];
#pragma unroll
    for (int o = 0; o < OUTN; o++) acc[o] = 0.f;

    for (int c = 0; c < CH; c += 4) {
        float4 H = *(const float4*)(g_a + base + c);
        const float hv[4] = {H.x, H.y, H.z, H.w};
#pragma unroll
        for (int q = 0; q < 4; q++)
#pragma unroll
            for (int o = 0; o < OUTN; o++) acc[o] = fmaf(hv[q], sw[o * CH + c + q], acc[o]);
    }

    const int mk = mask[b * LEN + l];
    float* yo = y + (b * LEN + l) * OUTN;
#pragma unroll
    for (int o = 0; o < OUTN; o++) yo[o] = mk ? (acc[o] + dec_b[o]) : 0.f;
}

// ============================================================================
// launch
// ============================================================================
extern "C" void kernel_launch(void* const* d_in, const int* in_sizes, int n_in,
                              void* d_out, int out_size) {
    const int*   x     = (const int*)d_in[0];
    const int*   mask  = (const int*)d_in[1];
    const float* emb   = (const float*)d_in[2];
    const float* w1    = (const float*)d_in[3];
    const float* b1    = (const float*)d_in[4];
    const float* w2    = (const float*)d_in[5];
    const float* b2    = (const float*)d_in[6];
    const float* dec_w = (const float*)d_in[7];
    const float* dec_b = (const float*)d_in[8];
    float*       y     = (float*)d_out;

    cudaFuncSetAttribute(conv_hmma_kernel, cudaFuncAttributeMaxDynamicSharedMemorySize, SMEM_SZ);

    // 1) repack weights (tf32-rounded, k-major)
    {
        const int total = NLEV * 2 * CH * KTOT;
        repack_kernel<<<(total + 255) / 256, 256>>>(w1, w2);
    }
    // 2) embedding gather -> act buffer A
    {
        const int total = BATCH * LEN * CH;
        embed_kernel<<<total / 256, 256>>>(x, emb);
    }
    // 3) TCN levels on tensor cores (1xTF32, 64x64 warp tiles)
    dim3 grid(LEN / TM, CH / TN, BATCH);
    for (int lev = 0; lev < NLEV; lev++) {
        const int d = 1 << lev;
        const int wb1 = (lev * 2 + 0) * CH * KTOT;
        const int wb2 = (lev * 2 + 1) * CH * KTOT;
        conv_hmma_kernel<<<grid, 128, SMEM_SZ>>>(wb1, b1 + lev * CH, d, 0);  // A -> B
        conv_hmma_kernel<<<grid, 128, SMEM_SZ>>>(wb2, b2 + lev * CH, d, 1);  // B (+res A) -> A
    }
    // 4) decode + mask
    decode_kernel<<<dim3(LEN / 128, BATCH), 128>>>(mask, dec_w, dec_b, y);
}